// round 13
// baseline (speedup 1.0000x reference)
#include <cuda_runtime.h>
#include <cuda_fp16.h>
#include <cstdint>

// Problem constants (from reference)
#define BATCH 16384
#define EMBED 1024
#define SEQ   7
#define E2    (EMBED / 2)       // 512 half2 (float2) lanes per full row
#define EQ2   128               // half2 lanes per quarter (256 channels)
#define NQ    4                 // channel quarters (grid.y)
#define ROWS_PER_CTA 16
#define ROWS_PER_IT  2          // 256 threads / 128 lanes
#define NIT (ROWS_PER_CTA / ROWS_PER_IT)   // 8 iterations
#define THREADS 256

// reinterpret helpers
__device__ __forceinline__ __half2 u2h2(unsigned r) {
    __half2 h; *reinterpret_cast<unsigned*>(&h) = r; return h;
}
__device__ __forceinline__ unsigned h22u(__half2 h) {
    return *reinterpret_cast<unsigned*>(&h);
}
// packed f16x2 tanh: one MUFU op for two channels
__device__ __forceinline__ __half2 tanh2h(__half2 x) {
    unsigned r = h22u(x);
    asm("tanh.approx.f16x2 %0, %0;" : "+r"(r));
    return u2h2(r);
}
// scaled float pair -> half2
__device__ __forceinline__ __half2 mk2(float2 v, float s) {
    return __floats2half2_rn(v.x * s, v.y * s);
}
__device__ __forceinline__ __half2 mk2b(float2 p, float2 q, float s) {
    return __floats2half2_rn((p.x + q.x) * s, (p.y + q.y) * s);
}
__device__ __forceinline__ __half2 mk3b(float2 p, float2 q, float2 r, float s) {
    return __floats2half2_rn((p.x + q.x + r.x) * s, (p.y + q.y + r.y) * s);
}

__device__ __forceinline__ uint32_t smem_u32(const void* p) {
    uint32_t a;
    asm("{ .reg .u64 t; cvta.to.shared.u64 t, %1; cvt.u32.u64 %0, t; }"
        : "=r"(a) : "l"(p));
    return a;
}

// Each thread owns ONE half2 stream (2 channels); gathers are prefetched one
// iteration ahead via cp.async into a smem double buffer (zero register cost,
// self-read so no CTA barrier needed). blockIdx.y = channel quarter.
__global__ void __launch_bounds__(THREADS, 6)
conv_cascade_q_kernel(const int* __restrict__ X,
                      const float2* __restrict__ emb,   // (VOCAB, E2)
                      const float2* __restrict__ c1,    // (2, E2)
                      const float2* __restrict__ c2,    // (2, E2)
                      const float2* __restrict__ c3,    // (3, E2)
                      const float2* __restrict__ c4,    // (3, E2)
                      float2* __restrict__ out)         // (BATCH, E2)
{
    const int tid  = threadIdx.x;
    const int lane = tid & (EQ2 - 1);                   // 0..127 half2 lane
    const int rsub = tid >> 7;                          // 0..1 row within iter
    const int e2   = blockIdx.y * EQ2 + lane;           // global half2 lane
    const int b0   = blockIdx.x * ROWS_PER_CTA;

    __shared__ int    idx[ROWS_PER_CTA][SEQ];
    __shared__ float2 ebuf[2][SEQ][THREADS];            // 28,672 B double buffer

    if (tid < ROWS_PER_CTA * SEQ) {
        int r = tid / SEQ;
        int t = tid % SEQ;
        idx[r][t] = X[(b0 + r) * SEQ + t];
    }

    // Tanh-domain scaled weights in registers (13 half2).
    float2 a0 = c1[0 * E2 + e2], a1 = c1[1 * E2 + e2];
    float2 d0 = c2[0 * E2 + e2], d1 = c2[1 * E2 + e2];
    float2 e0 = c3[0 * E2 + e2], e1 = c3[1 * E2 + e2], e2v = c3[2 * E2 + e2];
    float2 f0 = c4[0 * E2 + e2], f1 = c4[1 * E2 + e2], f2 = c4[2 * E2 + e2];

    const __half2 W10 = mk2(a0, 0.5f),  W11 = mk2(a1, 0.5f);
    const __half2 V0  = mk2(d0, 0.25f), V1  = mk2(d1, 0.25f);
    const __half2 B2  = mk2b(d0, d1, 0.25f);
    const __half2 U0  = mk2(e0, 0.25f), U1  = mk2(e1, 0.25f), U2 = mk2(e2v, 0.25f);
    const __half2 B3  = mk3b(e0, e1, e2v, 0.25f);
    const __half2 T0  = mk2(f0, 0.25f), T1  = mk2(f1, 0.25f), T2 = mk2(f2, 0.25f);
    const __half2 B4  = mk3b(f0, f1, f2, 0.25f);
    const __half2 HALF = __float2half2_rn(0.5f);

    __syncthreads();   // idx visible to all before any prefetch

    // Per-thread smem slot base (this thread's column in the buffer).
    const uint32_t slot = smem_u32(&ebuf[0][0][tid]);

    // Issue the 7 async copies for iteration `it` into buffer `buf`.
    auto issue = [&](int it, int buf) {
        const int r = it * ROWS_PER_IT + rsub;
#pragma unroll
        for (int t = 0; t < SEQ; ++t) {
            const float2* src = &emb[(long)idx[r][t] * E2 + e2];
            uint32_t dst = slot + (uint32_t)(buf * SEQ * THREADS + t * THREADS)
                                   * (uint32_t)sizeof(float2);
            asm volatile("cp.async.ca.shared.global [%0], [%1], 8;"
                         :: "r"(dst), "l"(src));
        }
        asm volatile("cp.async.commit_group;");
    };

    issue(0, 0);   // prologue

#pragma unroll 1
    for (int it = 0; it < NIT; ++it) {
        const int buf = it & 1;
        if (it + 1 < NIT) {
            issue(it + 1, buf ^ 1);
            asm volatile("cp.async.wait_group 1;");   // buffer `buf` ready
        } else {
            asm volatile("cp.async.wait_group 0;");
        }

        // Read this thread's 7 staged float2s, convert to half2.
        __half2 h[SEQ];
#pragma unroll
        for (int t = 0; t < SEQ; ++t) {
            float2 v = ebuf[buf][t][tid];
            h[t] = __floats2half2_rn(v.x, v.y);
        }

        // Stage 1 (size-2, raw input, scale 1/2, no bias)
        __half2 p[6];
#pragma unroll
        for (int t = 0; t < 6; ++t)
            p[t] = tanh2h(__hfma2(W10, h[t], __hmul2(W11, h[t + 1])));

        // Stage 2 (size-2, tanh-domain, scale 1/4 + bias)
        __half2 q[5];
#pragma unroll
        for (int t = 0; t < 5; ++t)
            q[t] = tanh2h(__hfma2(V0, p[t], __hfma2(V1, p[t + 1], B2)));

        // Stage 3 (size-3)
        __half2 s[3];
#pragma unroll
        for (int t = 0; t < 3; ++t)
            s[t] = tanh2h(__hfma2(U0, q[t],
                       __hfma2(U1, q[t + 1], __hfma2(U2, q[t + 2], B3))));

        // Stage 4 (size-3) + final affine back to sigma
        __half2 res = tanh2h(__hfma2(T0, s[0],
                        __hfma2(T1, s[1], __hfma2(T2, s[2], B4))));
        res = __hfma2(res, HALF, HALF);

        const int r = it * ROWS_PER_IT + rsub;
        __stcs(&out[(long)(b0 + r) * E2 + e2], __half22float2(res));
    }
}

extern "C" void kernel_launch(void* const* d_in, const int* in_sizes, int n_in,
                              void* d_out, int out_size)
{
    const int*    X    = (const int*)d_in[0];
    const float2* emb  = (const float2*)d_in[1];
    const float2* c1   = (const float2*)d_in[2];
    const float2* c2   = (const float2*)d_in[3];
    const float2* c3   = (const float2*)d_in[4];
    const float2* c4   = (const float2*)d_in[5];
    float2*       out  = (float2*)d_out;

    dim3 grid(BATCH / ROWS_PER_CTA, NQ);   // (1024, 4) — x fastest => quarter order
    dim3 block(THREADS);
    conv_cascade_q_kernel<<<grid, block>>>(X, emb, c1, c2, c3, c4, out);
}

// round 14
// speedup vs baseline: 1.1286x; 1.1286x over previous
#include <cuda_runtime.h>
#include <cuda_fp16.h>
#include <cstdint>

// Problem constants (from reference)
#define BATCH 16384
#define EMBED 1024
#define SEQ   7
#define E4    (EMBED / 4)       // 256 float4 lanes per full row
#define EQ4   64                // float4 lanes per quarter (256 channels)
#define NQ    4                 // channel quarters (grid.y)
#define ROWS_PER_CTA 16
#define ROWS_PER_IT  4          // 256 threads / 64 lanes
#define NIT (ROWS_PER_CTA / ROWS_PER_IT)  // 4
#define STAGED 5                // h[0..4] via cp.async; h[5],h[6] direct LDG
#define THREADS 256

// reinterpret helpers
__device__ __forceinline__ __half2 u2h2(unsigned r) {
    __half2 h; *reinterpret_cast<unsigned*>(&h) = r; return h;
}
__device__ __forceinline__ unsigned h22u(__half2 h) {
    return *reinterpret_cast<unsigned*>(&h);
}
// packed f16x2 tanh: one MUFU op for two channels
__device__ __forceinline__ __half2 tanh2h(__half2 x) {
    unsigned r = h22u(x);
    asm("tanh.approx.f16x2 %0, %0;" : "+r"(r));
    return u2h2(r);
}
__device__ __forceinline__ __half2 mk2(float a, float b, float s) {
    return __floats2half2_rn(a * s, b * s);
}
__device__ __forceinline__ uint32_t smem_u32(const void* p) {
    uint32_t a;
    asm("{ .reg .u64 t; cvta.to.shared.u64 t, %1; cvt.u32.u64 %0, t; }"
        : "=r"(a) : "l"(p));
    return a;
}

__global__ void __launch_bounds__(THREADS, 4)
conv_cascade_q_kernel(const int* __restrict__ X,
                      const float4* __restrict__ emb,   // (VOCAB, E4)
                      const float4* __restrict__ c1,    // (2, E4)
                      const float4* __restrict__ c2,    // (2, E4)
                      const float4* __restrict__ c3,    // (3, E4)
                      const float4* __restrict__ c4,    // (3, E4)
                      float4* __restrict__ out)         // (BATCH, E4)
{
    const int tid  = threadIdx.x;
    const int lane = tid & (EQ4 - 1);                   // 0..63
    const int rsub = tid >> 6;                          // 0..3
    const int e4   = blockIdx.y * EQ4 + lane;
    const int b0   = blockIdx.x * ROWS_PER_CTA;

    __shared__ float4 sbuf[2][STAGED][THREADS];         // 40,960 B (static OK)
    __shared__ int    idx[ROWS_PER_CTA][SEQ];

    if (tid < ROWS_PER_CTA * SEQ) {
        int r = tid / SEQ;
        int t = tid % SEQ;
        idx[r][t] = X[(b0 + r) * SEQ + t];
    }

    // Tanh-domain scaled weights in registers (f16x2; a = ch0/1, b = ch2/3).
    float4 a0 = c1[0 * E4 + e4], a1 = c1[1 * E4 + e4];
    float4 d0 = c2[0 * E4 + e4], d1 = c2[1 * E4 + e4];
    float4 e0 = c3[0 * E4 + e4], e1 = c3[1 * E4 + e4], e2 = c3[2 * E4 + e4];
    float4 f0 = c4[0 * E4 + e4], f1 = c4[1 * E4 + e4], f2 = c4[2 * E4 + e4];

    const __half2 W10a = mk2(a0.x, a0.y, 0.5f),  W10b = mk2(a0.z, a0.w, 0.5f);
    const __half2 W11a = mk2(a1.x, a1.y, 0.5f),  W11b = mk2(a1.z, a1.w, 0.5f);
    const __half2 V0a  = mk2(d0.x, d0.y, 0.25f), V0b  = mk2(d0.z, d0.w, 0.25f);
    const __half2 V1a  = mk2(d1.x, d1.y, 0.25f), V1b  = mk2(d1.z, d1.w, 0.25f);
    const __half2 B2a  = mk2(d0.x + d1.x, d0.y + d1.y, 0.25f);
    const __half2 B2b  = mk2(d0.z + d1.z, d0.w + d1.w, 0.25f);
    const __half2 U0a  = mk2(e0.x, e0.y, 0.25f), U0b  = mk2(e0.z, e0.w, 0.25f);
    const __half2 U1a  = mk2(e1.x, e1.y, 0.25f), U1b  = mk2(e1.z, e1.w, 0.25f);
    const __half2 U2a  = mk2(e2.x, e2.y, 0.25f), U2b  = mk2(e2.z, e2.w, 0.25f);
    const __half2 B3a  = mk2(e0.x + e1.x + e2.x, e0.y + e1.y + e2.y, 0.25f);
    const __half2 B3b  = mk2(e0.z + e1.z + e2.z, e0.w + e1.w + e2.w, 0.25f);
    const __half2 T0a  = mk2(f0.x, f0.y, 0.25f), T0b  = mk2(f0.z, f0.w, 0.25f);
    const __half2 T1a  = mk2(f1.x, f1.y, 0.25f), T1b  = mk2(f1.z, f1.w, 0.25f);
    const __half2 T2a  = mk2(f2.x, f2.y, 0.25f), T2b  = mk2(f2.z, f2.w, 0.25f);
    const __half2 B4a  = mk2(f0.x + f1.x + f2.x, f0.y + f1.y + f2.y, 0.25f);
    const __half2 B4b  = mk2(f0.z + f1.z + f2.z, f0.w + f1.w + f2.w, 0.25f);
    const __half2 HALF = __float2half2_rn(0.5f);

    __syncthreads();   // idx visible before any prefetch

    const uint32_t sbase = smem_u32(&sbuf[0][0][tid]);

    // Issue STAGED 16-byte cp.async copies for iteration `it` into buffer `buf`.
    auto issue = [&](int it, int buf) {
        const int r = it * ROWS_PER_IT + rsub;
#pragma unroll
        for (int t = 0; t < STAGED; ++t) {
            const float4* src = &emb[(long)idx[r][t] * E4 + e4];
            uint32_t dst = sbase +
                (uint32_t)((buf * STAGED + t) * THREADS) * (uint32_t)sizeof(float4);
            asm volatile("cp.async.cg.shared.global [%0], [%1], 16;"
                         :: "r"(dst), "l"(src));
        }
        asm volatile("cp.async.commit_group;");
    };

    issue(0, 0);   // prologue

#pragma unroll 1
    for (int it = 0; it < NIT; ++it) {
        const int buf = it & 1;
        const int r   = it * ROWS_PER_IT + rsub;

        // Direct gathers for the tail elements (consumed LAST in stage 1).
        float4 h5 = __ldg(&emb[(long)idx[r][5] * E4 + e4]);
        float4 h6 = __ldg(&emb[(long)idx[r][6] * E4 + e4]);

        if (it + 1 < NIT) {
            issue(it + 1, buf ^ 1);
            asm volatile("cp.async.wait_group 1;");   // current buffer ready
        } else {
            asm volatile("cp.async.wait_group 0;");
        }

        // Staged values -> half2 (self-read; no barrier needed).
        __half2 ha[SEQ], hb[SEQ];
#pragma unroll
        for (int t = 0; t < STAGED; ++t) {
            float4 v = sbuf[buf][t][tid];
            ha[t] = __floats2half2_rn(v.x, v.y);
            hb[t] = __floats2half2_rn(v.z, v.w);
        }

        // Stage 1: do t=0..3 first (staged data) to cover the h5/h6 LDGs.
        __half2 pa[6], pb[6];
#pragma unroll
        for (int t = 0; t < 4; ++t) {
            pa[t] = tanh2h(__hfma2(W10a, ha[t], __hmul2(W11a, ha[t + 1])));
            pb[t] = tanh2h(__hfma2(W10b, hb[t], __hmul2(W11b, hb[t + 1])));
        }
        ha[5] = __floats2half2_rn(h5.x, h5.y);
        hb[5] = __floats2half2_rn(h5.z, h5.w);
        pa[4] = tanh2h(__hfma2(W10a, ha[4], __hmul2(W11a, ha[5])));
        pb[4] = tanh2h(__hfma2(W10b, hb[4], __hmul2(W11b, hb[5])));
        ha[6] = __floats2half2_rn(h6.x, h6.y);
        hb[6] = __floats2half2_rn(h6.z, h6.w);
        pa[5] = tanh2h(__hfma2(W10a, ha[5], __hmul2(W11a, ha[6])));
        pb[5] = tanh2h(__hfma2(W10b, hb[5], __hmul2(W11b, hb[6])));

        // Stage 2 (size-2, tanh-domain)
        __half2 qa[5], qb[5];
#pragma unroll
        for (int t = 0; t < 5; ++t) {
            qa[t] = tanh2h(__hfma2(V0a, pa[t], __hfma2(V1a, pa[t + 1], B2a)));
            qb[t] = tanh2h(__hfma2(V0b, pb[t], __hfma2(V1b, pb[t + 1], B2b)));
        }

        // Stage 3 (size-3)
        __half2 sa[3], sb[3];
#pragma unroll
        for (int t = 0; t < 3; ++t) {
            sa[t] = tanh2h(__hfma2(U0a, qa[t],
                        __hfma2(U1a, qa[t + 1], __hfma2(U2a, qa[t + 2], B3a))));
            sb[t] = tanh2h(__hfma2(U0b, qb[t],
                        __hfma2(U1b, qb[t + 1], __hfma2(U2b, qb[t + 2], B3b))));
        }

        // Stage 4 (size-3) + final affine back to sigma
        __half2 ra = tanh2h(__hfma2(T0a, sa[0],
                       __hfma2(T1a, sa[1], __hfma2(T2a, sa[2], B4a))));
        __half2 rb = tanh2h(__hfma2(T0b, sb[0],
                       __hfma2(T1b, sb[1], __hfma2(T2b, sb[2], B4b))));
        ra = __hfma2(ra, HALF, HALF);
        rb = __hfma2(rb, HALF, HALF);

        float2 fa = __half22float2(ra);
        float2 fb = __half22float2(rb);
        __stcs(&out[(long)(b0 + r) * E4 + e4],
               make_float4(fa.x, fa.y, fb.x, fb.y));
    }
}

extern "C" void kernel_launch(void* const* d_in, const int* in_sizes, int n_in,
                              void* d_out, int out_size)
{
    const int*    X    = (const int*)d_in[0];
    const float4* emb  = (const float4*)d_in[1];
    const float4* c1   = (const float4*)d_in[2];
    const float4* c2   = (const float4*)d_in[3];
    const float4* c3   = (const float4*)d_in[4];
    const float4* c4   = (const float4*)d_in[5];
    float4*       out  = (float4*)d_out;

    dim3 grid(BATCH / ROWS_PER_CTA, NQ);   // (1024, 4) — x fastest => quarter order
    dim3 block(THREADS);
    conv_cascade_q_kernel<<<grid, block>>>(X, emb, c1, c2, c3, c4, out);
}